// round 8
// baseline (speedup 1.0000x reference)
#include <cuda_runtime.h>
#include <math.h>
#include <stdint.h>
#include <float.h>

#define N_    16
#define C_    64
#define F_    8
#define HW_   3136
#define NROWS (N_*C_*F_)     // 8192
#define ITER_ 128
#define OUT_  256
#define EPSV  1e-5

typedef unsigned long long ull;

// ---------------- scratch (static device memory; rewritten fully each run) ----
__device__ float  d_top5[NROWS*5];
__device__ double d_rsum[NROWS];
__device__ double d_rsq [NROWS];
__device__ float  d_si  [N_*C_*7*20];     // attention output, conv1 input
__device__ float  d_x1  [N_*ITER_*7*10];  // conv1 output (pre-BN)
__device__ double d_p1s [N_*ITER_];
__device__ double d_p1q [N_*ITER_];

// ---------------- helpers -----------------------------------------------------
__device__ __forceinline__ float ftanh(float x) {
    float y;
    asm("tanh.approx.f32 %0, %1;" : "=f"(y) : "f"(x));
    return y;
}
__device__ __forceinline__ ull pk2(float a, float b) {
    ull r; asm("mov.b64 %0, {%1, %2};" : "=l"(r) : "f"(a), "f"(b)); return r;
}
__device__ __forceinline__ void upk2(ull v, float& a, float& b) {
    asm("mov.b64 {%0, %1}, %2;" : "=f"(a), "=f"(b) : "l"(v));
}
__device__ __forceinline__ ull add2_(ull a, ull b) {
    ull r; asm("add.rn.f32x2 %0, %1, %2;" : "=l"(r) : "l"(a), "l"(b)); return r;
}
__device__ __forceinline__ ull fma2_(ull a, ull b, ull c) {
    ull r; asm("fma.rn.f32x2 %0, %1, %2, %3;" : "=l"(r) : "l"(a), "l"(b), "l"(c)); return r;
}

__device__ __forceinline__ void ins5(float* kk, float key) {
    if (key > kk[4]) {
        kk[4] = key;
        if (kk[4] > kk[3]) { float t=kk[4]; kk[4]=kk[3]; kk[3]=t;
        if (kk[3] > kk[2]) { t=kk[3]; kk[3]=kk[2]; kk[2]=t;
        if (kk[2] > kk[1]) { t=kk[2]; kk[2]=kk[1]; kk[1]=t;
        if (kk[1] > kk[0]) { t=kk[1]; kk[1]=kk[0]; kk[0]=t; } } } }
    }
}

// merge two sorted-descending 5-lists, keep top 5 (in a)
__device__ __forceinline__ void merge5(float* a, const float* b) {
    float r[5]; int ia = 0, ib = 0;
    #pragma unroll
    for (int t = 0; t < 5; t++) {
        float av = a[ia], bv = b[ib];
        if (av >= bv) { r[t] = av; ia++; } else { r[t] = bv; ib++; }
    }
    #pragma unroll
    for (int t = 0; t < 5; t++) a[t] = r[t];
}

// process 16 elements: packed f32x2 sums + one scalar-FMNMX screen per 16
template<bool NEG>
__device__ __forceinline__ void proc16(const float4 a, const float4 b,
                                       const float4 c, const float4 d,
                                       ull& s0, ull& s1, ull& q0, ull& q1,
                                       float* kk) {
    ull pa0 = pk2(a.x,a.y), pa1 = pk2(a.z,a.w);
    ull pb0 = pk2(b.x,b.y), pb1 = pk2(b.z,b.w);
    ull pc0 = pk2(c.x,c.y), pc1 = pk2(c.z,c.w);
    ull pd0 = pk2(d.x,d.y), pd1 = pk2(d.z,d.w);
    s0 = add2_(s0, pa0); s1 = add2_(s1, pa1);
    s0 = add2_(s0, pb0); s1 = add2_(s1, pb1);
    s0 = add2_(s0, pc0); s1 = add2_(s1, pc1);
    s0 = add2_(s0, pd0); s1 = add2_(s1, pd1);
    q0 = fma2_(pa0, pa0, q0); q1 = fma2_(pa1, pa1, q1);
    q0 = fma2_(pb0, pb0, q0); q1 = fma2_(pb1, pb1, q1);
    q0 = fma2_(pc0, pc0, q0); q1 = fma2_(pc1, pc1, q1);
    q0 = fma2_(pd0, pd0, q0); q1 = fma2_(pd1, pd1, q1);

    float x[16] = {a.x,a.y,a.z,a.w, b.x,b.y,b.z,b.w,
                   c.x,c.y,c.z,c.w, d.x,d.y,d.z,d.w};
    if (NEG) {
        #pragma unroll
        for (int j = 0; j < 16; j++) x[j] = -x[j];
    }
    float m01 = fmaxf(x[0],  x[1]),  m23 = fmaxf(x[2],  x[3]);
    float m45 = fmaxf(x[4],  x[5]),  m67 = fmaxf(x[6],  x[7]);
    float m89 = fmaxf(x[8],  x[9]),  mab = fmaxf(x[10], x[11]);
    float mcd = fmaxf(x[12], x[13]), mef = fmaxf(x[14], x[15]);
    float m0 = fmaxf(fmaxf(m01, m23), fmaxf(m45, m67));
    float m1 = fmaxf(fmaxf(m89, mab), fmaxf(mcd, mef));
    float m  = fmaxf(m0, m1);
    if (m > kk[4]) {
        #pragma unroll
        for (int j = 0; j < 16; j++) ins5(kk, x[j]);
    }
}

template<bool NEG>
__device__ __forceinline__ void proc4(const float4 a,
                                      ull& s0, ull& q0, float* kk) {
    ull p0 = pk2(a.x, a.y), p1 = pk2(a.z, a.w);
    s0 = add2_(s0, p0); s0 = add2_(s0, p1);
    q0 = fma2_(p0, p0, q0); q0 = fma2_(p1, p1, q0);
    float k0, k1v, k2, k3;
    if (NEG) { k0=-a.x; k1v=-a.y; k2=-a.z; k3=-a.w; }
    else     { k0= a.x; k1v= a.y; k2= a.z; k3= a.w; }
    float m = fmaxf(fmaxf(k0,k1v), fmaxf(k2,k3));
    if (m > kk[4]) { ins5(kk,k0); ins5(kk,k1v); ins5(kk,k2); ins5(kk,k3); }
}

// ---------------- K1: warp-per-row: top5 + sum/sumsq, packed f32x2 math --------
__global__ void __launch_bounds__(256) k1_top5(const float* __restrict__ h,
                                               const float* __restrict__ g0) {
    const int wid  = threadIdx.x >> 5, lane = threadIdx.x & 31;
    const int row  = blockIdx.x * 8 + wid;
    const int c    = (row >> 3) & (C_ - 1);
    const bool neg = (g0[c] < 0.f);

    const float4* p = (const float4*)(h + (size_t)row * HW_);

    ull s0 = 0ull, s1 = 0ull, q0 = 0ull, q1 = 0ull;   // packed (0.f, 0.f)
    float kk[5];
    #pragma unroll
    for (int j = 0; j < 5; j++) kk[j] = -FLT_MAX;

    if (!neg) {
        #pragma unroll 2
        for (int t = 0; t < 6; t++) {
            float4 a = p[lane + 128*t];
            float4 b = p[lane + 128*t + 32];
            float4 c4 = p[lane + 128*t + 64];
            float4 d = p[lane + 128*t + 96];
            proc16<false>(a, b, c4, d, s0, s1, q0, q1, kk);
        }
        if (lane < 16) proc4<false>(p[768 + lane], s0, q0, kk);
    } else {
        #pragma unroll 2
        for (int t = 0; t < 6; t++) {
            float4 a = p[lane + 128*t];
            float4 b = p[lane + 128*t + 32];
            float4 c4 = p[lane + 128*t + 64];
            float4 d = p[lane + 128*t + 96];
            proc16<true>(a, b, c4, d, s0, s1, q0, q1, kk);
        }
        if (lane < 16) proc4<true>(p[768 + lane], s0, q0, kk);
    }

    // combine packed halves
    ull st = add2_(s0, s1);
    ull qt = add2_(q0, q1);
    float slo, shi, qlo, qhi;
    upk2(st, slo, shi); upk2(qt, qlo, qhi);
    float s = slo + shi, q = qlo + qhi;

    // warp butterfly reduce
    const unsigned m = 0xffffffffu;
    #pragma unroll
    for (int off = 16; off > 0; off >>= 1) {
        float ob[5];
        #pragma unroll
        for (int j = 0; j < 5; j++) ob[j] = __shfl_xor_sync(m, kk[j], off);
        merge5(kk, ob);
        s += __shfl_xor_sync(m, s, off);
        q += __shfl_xor_sync(m, q, off);
    }

    if (lane == 0) {
        const float sel = neg ? -1.f : 1.f;
        #pragma unroll
        for (int j = 0; j < 5; j++) d_top5[row*5 + j] = kk[j] * sel;
        d_rsum[row] = (double)s;
        d_rsq [row] = (double)q;
    }
}

// ---------------- K3: per-(n,c) block: BN0 finalize + attention pipeline -------
__global__ void __launch_bounds__(256) k3_attn(
    const float* __restrict__ g0,  const float* __restrict__ b0,
    const float* __restrict__ up_w, const float* __restrict__ up_b,
    const float* __restrict__ up2_w, const float* __restrict__ up2_b,
    const float* __restrict__ up3_w, const float* __restrict__ up3_b,
    const float* __restrict__ wW,   const float* __restrict__ wproj,
    const float* __restrict__ wW2,  const float* __restrict__ wproj2) {

    const int bid = blockIdx.x;     // n*64 + c
    const int tid = threadIdx.x;
    const int n = bid >> 6, c = bid & 63;

    __shared__ double s1[128], s2[128];
    __shared__ float  s_scale, s_shift;
    __shared__ float  sm_t[8][25], sm_u[8][25];
    __shared__ float  sm_s5[8][5], sm_w5[8][5];
    __shared__ float  sm_cen[8][2];
    __shared__ float  sm_cen20[7][20], sm_u2p[7][20];
    __shared__ float  sm_s2[7], sm_att2[7];

    if (tid < 128) {
        int n2 = tid >> 3, f = tid & 7;
        int r = (n2*C_ + c)*F_ + f;
        s1[tid] = d_rsum[r];
        s2[tid] = d_rsq [r];
    }
    __syncthreads();
    for (int st = 64; st > 0; st >>= 1) {
        if (tid < st) { s1[tid] += s1[tid+st]; s2[tid] += s2[tid+st]; }
        __syncthreads();
    }
    if (tid == 0) {
        double cnt  = (double)(N_ * F_ * HW_);
        double mean = s1[0] / cnt;
        double var  = s2[0] / cnt - mean*mean;
        double inv  = rsqrt(var + EPSV);
        float  sc   = (float)((double)g0[c] * inv);
        s_scale = sc;
        s_shift = b0[c] - (float)mean * sc;
    }
    __syncthreads();

    const int f = tid >> 5, lane = tid & 31;   // 8 warps = 8 frames
    const int row = (n*C_ + c)*F_ + f;

    float v[5];
    #pragma unroll
    for (int j = 0; j < 5; j++) v[j] = d_top5[row*5 + j] * s_scale + s_shift;

    if (lane < 25) {
        float a = up2_b[lane];
        #pragma unroll
        for (int j = 0; j < 5; j++) a += v[j] * up2_w[lane*5 + j];
        sm_t[f][lane] = a;
    }
    __syncwarp();
    if (lane < 25) {
        float a = 0.f;
        #pragma unroll
        for (int k = 0; k < 25; k++) a += sm_t[f][k] * wW[k*25 + lane];
        sm_u[f][lane] = ftanh(a);
    }
    __syncwarp();
    if (lane < 5) {
        float a = 0.f;
        #pragma unroll
        for (int k = 0; k < 25; k++) a += sm_u[f][k] * wproj[k*5 + lane];
        sm_s5[f][lane] = a;
    }
    __syncwarp();
    if (lane < 5) {
        float mx = sm_s5[f][0];
        #pragma unroll
        for (int j = 1; j < 5; j++) mx = fmaxf(mx, sm_s5[f][j]);
        float se = 0.f;
        #pragma unroll
        for (int j = 0; j < 5; j++) se += __expf(sm_s5[f][j] - mx);
        float att = __expf(sm_s5[f][lane] - mx) / se;
        float a = up3_b[lane];
        #pragma unroll
        for (int k = 0; k < 25; k++) a += sm_t[f][k] * up3_w[lane*25 + k];
        sm_w5[f][lane] = a * att;
    }
    __syncwarp();
    float p0 = 0.f, p1 = 0.f;
    if (lane < 25) {
        float a = up2_b[lane];
        #pragma unroll
        for (int j = 0; j < 5; j++) a += sm_w5[f][j] * up2_w[lane*5 + j];
        p0 = a * (float)(lane / 5);
        p1 = a * (float)(lane % 5);
    }
    #pragma unroll
    for (int off = 16; off > 0; off >>= 1) {
        p0 += __shfl_down_sync(0xffffffffu, p0, off);
        p1 += __shfl_down_sync(0xffffffffu, p1, off);
    }
    if (lane == 0) { sm_cen[f][0] = p0; sm_cen[f][1] = p1; }
    __syncthreads();

    if (tid < 140) {
        int j = tid / 20, k = tid % 20;
        float d0 = sm_cen[j+1][0] - sm_cen[j][0];
        float d1 = sm_cen[j+1][1] - sm_cen[j][1];
        sm_cen20[j][k] = d0 * up_w[k*2] + d1 * up_w[k*2 + 1] + up_b[k];
    }
    __syncthreads();
    if (tid < 140) {
        int i = tid / 20, k = tid % 20;
        float a = 0.f;
        #pragma unroll
        for (int j = 0; j < 7; j++) a += wW2[i*7 + j] * sm_cen20[j][k];
        sm_u2p[i][k] = ftanh(a) * wproj2[k];
    }
    __syncthreads();
    if (tid < 7) {
        float a = 0.f;
        #pragma unroll
        for (int k = 0; k < 20; k++) a += sm_u2p[tid][k];
        sm_s2[tid] = a;
    }
    __syncthreads();
    if (tid < 7) {
        float mx = sm_s2[0];
        #pragma unroll
        for (int i = 1; i < 7; i++) mx = fmaxf(mx, sm_s2[i]);
        float se = 0.f;
        #pragma unroll
        for (int i = 0; i < 7; i++) se += __expf(sm_s2[i] - mx);
        sm_att2[tid] = __expf(sm_s2[tid] - mx) / se;
    }
    __syncthreads();
    if (tid < 140) {
        int j = tid / 20, k = tid % 20;
        d_si[(bid*7 + j)*20 + k] = sm_cen20[j][k] * sm_att2[j];
    }
}

// ---------------- K4: conv1 (64->128, k=(1,3), s=(1,2), p=(0,1)) + BN1 partials
// Register-blocked: 1 thread = one (oc, i) row, 10 outputs.
__global__ void __launch_bounds__(128) k4_conv1(const float* __restrict__ w1) {
    __shared__ float s_si[C_*140];   // 8960 floats
    __shared__ float s_w[16*192];    // 3072 floats
    __shared__ float sp[112], sq[112];

    const int bid = blockIdx.x, tid = threadIdx.x;
    const int n = bid >> 3, gid = bid & 7;
    const int ocbase = gid * 16;

    const float* src = d_si + n * (C_*140);
    for (int i = tid; i < C_*140; i += 128) s_si[i] = src[i];
    for (int i = tid; i < 16*192; i += 128) s_w[i]  = w1[ocbase*192 + i];
    __syncthreads();

    if (tid < 112) {
        const int ocl = tid / 7, i = tid % 7;
        const int oc = ocbase + ocl;
        float acc[10];
        #pragma unroll
        for (int j = 0; j < 10; j++) acc[j] = 0.f;
        const float* wp = &s_w[ocl*192];

        #pragma unroll 4
        for (int ic = 0; ic < 64; ic++) {
            const float* xp = &s_si[ic*140 + i*20];
            float4 v0 = *(const float4*)(xp);
            float4 v1 = *(const float4*)(xp + 4);
            float4 v2 = *(const float4*)(xp + 8);
            float4 v3 = *(const float4*)(xp + 12);
            float4 v4 = *(const float4*)(xp + 16);
            float x[20] = {v0.x,v0.y,v0.z,v0.w, v1.x,v1.y,v1.z,v1.w,
                           v2.x,v2.y,v2.z,v2.w, v3.x,v3.y,v3.z,v3.w,
                           v4.x,v4.y,v4.z,v4.w};
            float w0 = wp[ic*3], wv1 = wp[ic*3+1], wv2 = wp[ic*3+2];
            acc[0] += x[0]*wv1 + x[1]*wv2;
            #pragma unroll
            for (int ow = 1; ow < 10; ow++)
                acc[ow] += x[2*ow-1]*w0 + x[2*ow]*wv1 + x[2*ow+1]*wv2;
        }
        float ssum = 0.f, ssq = 0.f;
        float* op = &d_x1[((n*ITER_ + oc)*7 + i)*10];
        #pragma unroll
        for (int ow = 0; ow < 10; ow++) {
            op[ow] = acc[ow]; ssum += acc[ow]; ssq += acc[ow]*acc[ow];
        }
        sp[tid] = ssum; sq[tid] = ssq;
    }
    __syncthreads();
    if (tid < 16) {
        double S = 0.0, Q = 0.0;
        #pragma unroll
        for (int j = 0; j < 7; j++) { S += sp[tid*7+j]; Q += sq[tid*7+j]; }
        d_p1s[n*ITER_ + ocbase + tid] = S;
        d_p1q[n*ITER_ + ocbase + tid] = Q;
    }
}

// ---------------- K67: BN1+tanh (in-block) + conv2 + BN2 + tanh + mean -> out --
// 64 blocks (4 oc each) x 256 thr; loops 16 n, cp.async double-buffered raw x1.
// smem floats: s_raw 2*8960 | s_x 10752 | s_w 1536 | s_part 1120 | s_x2 2240
//              s_ss 28 | s_sq 28 | s_sc2 4 | s_sh2 4 | s_sc1 128 | s_sh1 128
#define K67_SMEM 33888
__global__ void __launch_bounds__(256) k67_conv2(const float* __restrict__ w2,
                                                 const float* __restrict__ g1,
                                                 const float* __restrict__ b1,
                                                 const float* __restrict__ g2,
                                                 const float* __restrict__ b2,
                                                 float* __restrict__ out) {
    extern __shared__ float sm7[];
    float* s_raw  = sm7;                  // 2 * 8960
    float* s_x    = sm7 + 17920;          // 10752 (128 ic * 84, rows of 10 pad 12)
    float* s_w    = sm7 + 28672;          // 1536
    float* s_part = sm7 + 30208;          // 1120
    float* s_x2   = sm7 + 31328;          // 2240
    float* s_ss   = sm7 + 33568;          // 28
    float* s_sq   = sm7 + 33596;          // 28
    float* s_sc2  = sm7 + 33624;          // 4
    float* s_sh2  = sm7 + 33628;          // 4
    float* s_sc1  = sm7 + 33632;          // 128
    float* s_sh1  = sm7 + 33760;          // 128

    const int tid = threadIdx.x;
    const int ocbase = blockIdx.x * 4;

    for (int i = tid; i < 4*384; i += 256) s_w[i] = w2[ocbase*384 + i];

    // BN1 scale/shift (all 128 ic, per block — cheap)
    if (tid < 128) {
        double S = 0.0, Q = 0.0;
        #pragma unroll
        for (int n2 = 0; n2 < 16; n2++) {
            S += d_p1s[n2*ITER_ + tid];
            Q += d_p1q[n2*ITER_ + tid];
        }
        double cnt  = (double)(N_ * 7 * 10);
        double mean = S / cnt;
        double var  = Q / cnt - mean*mean;
        float sc = (float)((double)g1[tid] * rsqrt(var + EPSV));
        s_sc1[tid] = sc;
        s_sh1[tid] = b1[tid] - (float)mean * sc;
    }

    // prologue: async copy raw x1[n=0] into buffer 0 (8960 floats = 2240 x 16B)
    {
        const float* src = d_x1;
        for (int i = tid; i < 2240; i += 256) {
            unsigned dst = (unsigned)__cvta_generic_to_shared(s_raw + i*4);
            asm volatile("cp.async.cg.shared.global [%0], [%1], 16;"
                         :: "r"(dst), "l"(src + i*4));
        }
        asm volatile("cp.async.commit_group;" ::: "memory");
    }

    // conv task mapping (tid < 224): g = ic-split group, (ocl, ii) output row
    const int g   = tid / 28;
    const int rr  = tid - g*28;
    const int ocl = rr / 7;
    const int ii  = rr - ocl*7;
    float accS = 0.f, accQ = 0.f;

    for (int n = 0; n < 16; n++) {
        asm volatile("cp.async.wait_group 0;" ::: "memory");
        __syncthreads();
        const float* rawp = s_raw + (n & 1) * 8960;

        if (n < 15) {
            float* nb = s_raw + ((n + 1) & 1) * 8960;
            const float* src = d_x1 + (n + 1) * 8960;
            for (int i = tid; i < 2240; i += 256) {
                unsigned dst = (unsigned)__cvta_generic_to_shared(nb + i*4);
                asm volatile("cp.async.cg.shared.global [%0], [%1], 16;"
                             :: "r"(dst), "l"(src + i*4));
            }
            asm volatile("cp.async.commit_group;" ::: "memory");
        }

        // transform: tanh(BN1(raw)) into padded layout; 896 rows of 10
        for (int r0 = tid; r0 < 896; r0 += 256) {
            int ic = r0 / 7, i = r0 - ic*7;
            const float* rp = rawp + ic*70 + i*10;
            float* xp = s_x + ic*84 + i*12;
            float sc = s_sc1[ic], sh = s_sh1[ic];
            #pragma unroll
            for (int ow = 0; ow < 10; ow++) xp[ow] = ftanh(rp[ow]*sc + sh);
        }
        __syncthreads();

        if (tid < 224) {
            float acc[5];
            #pragma unroll
            for (int j = 0; j < 5; j++) acc[j] = 0.f;
            const float* wp = &s_w[ocl*384];
            const int ic0 = g * 16;
            #pragma unroll 4
            for (int ic = ic0; ic < ic0 + 16; ic++) {
                const float* xp = &s_x[ic*84 + ii*12];
                float4 v0 = *(const float4*)(xp);
                float4 v1 = *(const float4*)(xp + 4);
                float2 v2 = *(const float2*)(xp + 8);
                float x[10] = {v0.x,v0.y,v0.z,v0.w, v1.x,v1.y,v1.z,v1.w, v2.x,v2.y};
                float w0 = wp[ic*3], wv1 = wp[ic*3+1], wv2 = wp[ic*3+2];
                acc[0] += x[0]*wv1 + x[1]*wv2;
                #pragma unroll
                for (int ow = 1; ow < 5; ow++)
                    acc[ow] += x[2*ow-1]*w0 + x[2*ow]*wv1 + x[2*ow+1]*wv2;
            }
            float* pp = &s_part[(g*28 + ocl*7 + ii)*5];
            #pragma unroll
            for (int ow = 0; ow < 5; ow++) pp[ow] = acc[ow];
        }
        __syncthreads();
        if (tid < 28) {
            const int oc2 = tid / 7, i2 = tid - oc2*7;
            #pragma unroll
            for (int ow = 0; ow < 5; ow++) {
                float a = 0.f;
                #pragma unroll
                for (int gg = 0; gg < 8; gg++)
                    a += s_part[(gg*28 + oc2*7 + i2)*5 + ow];
                s_x2[(oc2*16 + n)*35 + i2*5 + ow] = a;
                accS += a; accQ += a*a;
            }
        }
        // next-iter loop-top __syncthreads guards s_x / s_part reuse
    }
    __syncthreads();
    if (tid < 28) { s_ss[tid] = accS; s_sq[tid] = accQ; }
    __syncthreads();
    if (tid < 4) {
        float S = 0.f, Q = 0.f;
        #pragma unroll
        for (int j = 0; j < 7; j++) { S += s_ss[tid*7+j]; Q += s_sq[tid*7+j]; }
        double cnt  = (double)(N_ * 7 * 5);
        double mean = (double)S / cnt;
        double var  = (double)Q / cnt - mean*mean;
        float sc = (float)((double)g2[ocbase + tid] * rsqrt(var + EPSV));
        s_sc2[tid] = sc;
        s_sh2[tid] = b2[ocbase + tid] - (float)mean * sc;
    }
    __syncthreads();
    for (int t = tid; t < 448; t += 256) {
        int n = t / 28, r2 = t - n*28, oc2 = r2 / 7, i2 = r2 - oc2*7;
        const float* xp = &s_x2[(oc2*16 + n)*35 + i2*5];
        float sc = s_sc2[oc2], sh = s_sh2[oc2];
        float a = 0.f;
        #pragma unroll
        for (int w = 0; w < 5; w++) a += ftanh(xp[w] * sc + sh);
        out[(n*OUT_ + (ocbase + oc2))*7 + i2] = a * 0.2f;
    }
}

// ---------------- launcher ----------------------------------------------------
extern "C" void kernel_launch(void* const* d_in, const int* in_sizes, int n_in,
                              void* d_out, int out_size) {
    (void)in_sizes; (void)n_in; (void)out_size;
    const float* h      = (const float*)d_in[0];
    const float* g0     = (const float*)d_in[1];
    const float* b0     = (const float*)d_in[2];
    const float* up_w   = (const float*)d_in[3];
    const float* up_b   = (const float*)d_in[4];
    const float* up2_w  = (const float*)d_in[5];
    const float* up2_b  = (const float*)d_in[6];
    const float* up3_w  = (const float*)d_in[7];
    const float* up3_b  = (const float*)d_in[8];
    const float* wW     = (const float*)d_in[9];
    const float* wproj  = (const float*)d_in[10];
    const float* wW2    = (const float*)d_in[11];
    const float* wproj2 = (const float*)d_in[12];
    const float* w1     = (const float*)d_in[13];
    const float* g1     = (const float*)d_in[14];
    const float* b1     = (const float*)d_in[15];
    const float* w2     = (const float*)d_in[16];
    const float* g2     = (const float*)d_in[17];
    const float* b2     = (const float*)d_in[18];
    float* out = (float*)d_out;

    cudaFuncSetAttribute(k67_conv2, cudaFuncAttributeMaxDynamicSharedMemorySize,
                         K67_SMEM * 4);

    k1_top5<<<1024, 256>>>(h, g0);
    k3_attn<<<N_*C_, 256>>>(g0, b0, up_w, up_b, up2_w, up2_b, up3_w, up3_b,
                            wW, wproj, wW2, wproj2);
    k4_conv1<<<128, 128>>>(w1);
    k67_conv2<<<64, 256, K67_SMEM * 4>>>(w2, g1, b1, g2, b2, out);
}

// round 10
// speedup vs baseline: 1.1535x; 1.1535x over previous
#include <cuda_runtime.h>
#include <math.h>
#include <stdint.h>
#include <float.h>

#define N_    16
#define C_    64
#define F_    8
#define HW_   3136
#define NROWS (N_*C_*F_)     // 8192
#define ITER_ 128
#define OUT_  256
#define EPSV  1e-5

typedef unsigned long long ull;

// ---------------- scratch (static device memory; rewritten fully each run) ----
__device__ float  d_top5[NROWS*5];
__device__ double d_rsum[NROWS];
__device__ double d_rsq [NROWS];
__device__ float  d_si  [N_*C_*7*20];     // attention output, conv1 input
__device__ float  d_x1  [N_*ITER_*7*10];  // conv1 output (pre-BN)
__device__ float  d_x1t [N_*ITER_*7*12];  // tanh(BN1(x1)), padded rows of 12
__device__ double d_p1s [N_*ITER_];
__device__ double d_p1q [N_*ITER_];

// ---------------- helpers -----------------------------------------------------
__device__ __forceinline__ float ftanh(float x) {
    float y;
    asm("tanh.approx.f32 %0, %1;" : "=f"(y) : "f"(x));
    return y;
}
__device__ __forceinline__ ull pk2(float a, float b) {
    ull r; asm("mov.b64 %0, {%1, %2};" : "=l"(r) : "f"(a), "f"(b)); return r;
}
__device__ __forceinline__ void upk2(ull v, float& a, float& b) {
    asm("mov.b64 {%0, %1}, %2;" : "=f"(a), "=f"(b) : "l"(v));
}
__device__ __forceinline__ ull add2_(ull a, ull b) {
    ull r; asm("add.rn.f32x2 %0, %1, %2;" : "=l"(r) : "l"(a), "l"(b)); return r;
}
__device__ __forceinline__ ull fma2_(ull a, ull b, ull c) {
    ull r; asm("fma.rn.f32x2 %0, %1, %2, %3;" : "=l"(r) : "l"(a), "l"(b), "l"(c)); return r;
}

__device__ __forceinline__ void ins5(float* kk, float key) {
    if (key > kk[4]) {
        kk[4] = key;
        if (kk[4] > kk[3]) { float t=kk[4]; kk[4]=kk[3]; kk[3]=t;
        if (kk[3] > kk[2]) { t=kk[3]; kk[3]=kk[2]; kk[2]=t;
        if (kk[2] > kk[1]) { t=kk[2]; kk[2]=kk[1]; kk[1]=t;
        if (kk[1] > kk[0]) { t=kk[1]; kk[1]=kk[0]; kk[0]=t; } } } }
    }
}

// merge two sorted-descending 5-lists, keep top 5 (in a)
__device__ __forceinline__ void merge5(float* a, const float* b) {
    float r[5]; int ia = 0, ib = 0;
    #pragma unroll
    for (int t = 0; t < 5; t++) {
        float av = a[ia], bv = b[ib];
        if (av >= bv) { r[t] = av; ia++; } else { r[t] = bv; ib++; }
    }
    #pragma unroll
    for (int t = 0; t < 5; t++) a[t] = r[t];
}

// process 16 elements: packed f32x2 sums + one scalar-FMNMX screen per 16
template<bool NEG>
__device__ __forceinline__ void proc16(const float4 a, const float4 b,
                                       const float4 c, const float4 d,
                                       ull& s0, ull& s1, ull& q0, ull& q1,
                                       float* kk) {
    ull pa0 = pk2(a.x,a.y), pa1 = pk2(a.z,a.w);
    ull pb0 = pk2(b.x,b.y), pb1 = pk2(b.z,b.w);
    ull pc0 = pk2(c.x,c.y), pc1 = pk2(c.z,c.w);
    ull pd0 = pk2(d.x,d.y), pd1 = pk2(d.z,d.w);
    s0 = add2_(s0, pa0); s1 = add2_(s1, pa1);
    s0 = add2_(s0, pb0); s1 = add2_(s1, pb1);
    s0 = add2_(s0, pc0); s1 = add2_(s1, pc1);
    s0 = add2_(s0, pd0); s1 = add2_(s1, pd1);
    q0 = fma2_(pa0, pa0, q0); q1 = fma2_(pa1, pa1, q1);
    q0 = fma2_(pb0, pb0, q0); q1 = fma2_(pb1, pb1, q1);
    q0 = fma2_(pc0, pc0, q0); q1 = fma2_(pc1, pc1, q1);
    q0 = fma2_(pd0, pd0, q0); q1 = fma2_(pd1, pd1, q1);

    float x[16] = {a.x,a.y,a.z,a.w, b.x,b.y,b.z,b.w,
                   c.x,c.y,c.z,c.w, d.x,d.y,d.z,d.w};
    if (NEG) {
        #pragma unroll
        for (int j = 0; j < 16; j++) x[j] = -x[j];
    }
    float m01 = fmaxf(x[0],  x[1]),  m23 = fmaxf(x[2],  x[3]);
    float m45 = fmaxf(x[4],  x[5]),  m67 = fmaxf(x[6],  x[7]);
    float m89 = fmaxf(x[8],  x[9]),  mab = fmaxf(x[10], x[11]);
    float mcd = fmaxf(x[12], x[13]), mef = fmaxf(x[14], x[15]);
    float m0 = fmaxf(fmaxf(m01, m23), fmaxf(m45, m67));
    float m1 = fmaxf(fmaxf(m89, mab), fmaxf(mcd, mef));
    float m  = fmaxf(m0, m1);
    if (m > kk[4]) {
        #pragma unroll
        for (int j = 0; j < 16; j++) ins5(kk, x[j]);
    }
}

template<bool NEG>
__device__ __forceinline__ void proc4(const float4 a,
                                      ull& s0, ull& q0, float* kk) {
    ull p0 = pk2(a.x, a.y), p1 = pk2(a.z, a.w);
    s0 = add2_(s0, p0); s0 = add2_(s0, p1);
    q0 = fma2_(p0, p0, q0); q0 = fma2_(p1, p1, q0);
    float k0, k1v, k2, k3;
    if (NEG) { k0=-a.x; k1v=-a.y; k2=-a.z; k3=-a.w; }
    else     { k0= a.x; k1v= a.y; k2= a.z; k3= a.w; }
    float m = fmaxf(fmaxf(k0,k1v), fmaxf(k2,k3));
    if (m > kk[4]) { ins5(kk,k0); ins5(kk,k1v); ins5(kk,k2); ins5(kk,k3); }
}

// ---------------- K1: warp-per-row: top5 + sum/sumsq, packed f32x2 math --------
__global__ void __launch_bounds__(256) k1_top5(const float* __restrict__ h,
                                               const float* __restrict__ g0) {
    const int wid  = threadIdx.x >> 5, lane = threadIdx.x & 31;
    const int row  = blockIdx.x * 8 + wid;
    const int c    = (row >> 3) & (C_ - 1);
    const bool neg = (g0[c] < 0.f);

    const float4* p = (const float4*)(h + (size_t)row * HW_);

    ull s0 = 0ull, s1 = 0ull, q0 = 0ull, q1 = 0ull;   // packed (0.f, 0.f)
    float kk[5];
    #pragma unroll
    for (int j = 0; j < 5; j++) kk[j] = -FLT_MAX;

    if (!neg) {
        #pragma unroll 2
        for (int t = 0; t < 6; t++) {
            float4 a = p[lane + 128*t];
            float4 b = p[lane + 128*t + 32];
            float4 c4 = p[lane + 128*t + 64];
            float4 d = p[lane + 128*t + 96];
            proc16<false>(a, b, c4, d, s0, s1, q0, q1, kk);
        }
        if (lane < 16) proc4<false>(p[768 + lane], s0, q0, kk);
    } else {
        #pragma unroll 2
        for (int t = 0; t < 6; t++) {
            float4 a = p[lane + 128*t];
            float4 b = p[lane + 128*t + 32];
            float4 c4 = p[lane + 128*t + 64];
            float4 d = p[lane + 128*t + 96];
            proc16<true>(a, b, c4, d, s0, s1, q0, q1, kk);
        }
        if (lane < 16) proc4<true>(p[768 + lane], s0, q0, kk);
    }

    // combine packed halves
    ull st = add2_(s0, s1);
    ull qt = add2_(q0, q1);
    float slo, shi, qlo, qhi;
    upk2(st, slo, shi); upk2(qt, qlo, qhi);
    float s = slo + shi, q = qlo + qhi;

    // warp butterfly reduce
    const unsigned m = 0xffffffffu;
    #pragma unroll
    for (int off = 16; off > 0; off >>= 1) {
        float ob[5];
        #pragma unroll
        for (int j = 0; j < 5; j++) ob[j] = __shfl_xor_sync(m, kk[j], off);
        merge5(kk, ob);
        s += __shfl_xor_sync(m, s, off);
        q += __shfl_xor_sync(m, q, off);
    }

    if (lane == 0) {
        const float sel = neg ? -1.f : 1.f;
        #pragma unroll
        for (int j = 0; j < 5; j++) d_top5[row*5 + j] = kk[j] * sel;
        d_rsum[row] = (double)s;
        d_rsq [row] = (double)q;
    }
}

// ---------------- K3: per-(n,c) block: BN0 finalize + attention pipeline -------
__global__ void __launch_bounds__(256) k3_attn(
    const float* __restrict__ g0,  const float* __restrict__ b0,
    const float* __restrict__ up_w, const float* __restrict__ up_b,
    const float* __restrict__ up2_w, const float* __restrict__ up2_b,
    const float* __restrict__ up3_w, const float* __restrict__ up3_b,
    const float* __restrict__ wW,   const float* __restrict__ wproj,
    const float* __restrict__ wW2,  const float* __restrict__ wproj2) {

    const int bid = blockIdx.x;     // n*64 + c
    const int tid = threadIdx.x;
    const int n = bid >> 6, c = bid & 63;

    __shared__ double s1[128], s2[128];
    __shared__ float  s_scale, s_shift;
    __shared__ float  sm_t[8][25], sm_u[8][25];
    __shared__ float  sm_s5[8][5], sm_w5[8][5];
    __shared__ float  sm_cen[8][2];
    __shared__ float  sm_cen20[7][20], sm_u2p[7][20];
    __shared__ float  sm_s2[7], sm_att2[7];

    if (tid < 128) {
        int n2 = tid >> 3, f = tid & 7;
        int r = (n2*C_ + c)*F_ + f;
        s1[tid] = d_rsum[r];
        s2[tid] = d_rsq [r];
    }
    __syncthreads();
    for (int st = 64; st > 0; st >>= 1) {
        if (tid < st) { s1[tid] += s1[tid+st]; s2[tid] += s2[tid+st]; }
        __syncthreads();
    }
    if (tid == 0) {
        double cnt  = (double)(N_ * F_ * HW_);
        double mean = s1[0] / cnt;
        double var  = s2[0] / cnt - mean*mean;
        double inv  = rsqrt(var + EPSV);
        float  sc   = (float)((double)g0[c] * inv);
        s_scale = sc;
        s_shift = b0[c] - (float)mean * sc;
    }
    __syncthreads();

    const int f = tid >> 5, lane = tid & 31;   // 8 warps = 8 frames
    const int row = (n*C_ + c)*F_ + f;

    float v[5];
    #pragma unroll
    for (int j = 0; j < 5; j++) v[j] = d_top5[row*5 + j] * s_scale + s_shift;

    if (lane < 25) {
        float a = up2_b[lane];
        #pragma unroll
        for (int j = 0; j < 5; j++) a += v[j] * up2_w[lane*5 + j];
        sm_t[f][lane] = a;
    }
    __syncwarp();
    if (lane < 25) {
        float a = 0.f;
        #pragma unroll
        for (int k = 0; k < 25; k++) a += sm_t[f][k] * wW[k*25 + lane];
        sm_u[f][lane] = ftanh(a);
    }
    __syncwarp();
    if (lane < 5) {
        float a = 0.f;
        #pragma unroll
        for (int k = 0; k < 25; k++) a += sm_u[f][k] * wproj[k*5 + lane];
        sm_s5[f][lane] = a;
    }
    __syncwarp();
    if (lane < 5) {
        float mx = sm_s5[f][0];
        #pragma unroll
        for (int j = 1; j < 5; j++) mx = fmaxf(mx, sm_s5[f][j]);
        float se = 0.f;
        #pragma unroll
        for (int j = 0; j < 5; j++) se += __expf(sm_s5[f][j] - mx);
        float att = __expf(sm_s5[f][lane] - mx) / se;
        float a = up3_b[lane];
        #pragma unroll
        for (int k = 0; k < 25; k++) a += sm_t[f][k] * up3_w[lane*25 + k];
        sm_w5[f][lane] = a * att;
    }
    __syncwarp();
    float p0 = 0.f, p1 = 0.f;
    if (lane < 25) {
        float a = up2_b[lane];
        #pragma unroll
        for (int j = 0; j < 5; j++) a += sm_w5[f][j] * up2_w[lane*5 + j];
        p0 = a * (float)(lane / 5);
        p1 = a * (float)(lane % 5);
    }
    #pragma unroll
    for (int off = 16; off > 0; off >>= 1) {
        p0 += __shfl_down_sync(0xffffffffu, p0, off);
        p1 += __shfl_down_sync(0xffffffffu, p1, off);
    }
    if (lane == 0) { sm_cen[f][0] = p0; sm_cen[f][1] = p1; }
    __syncthreads();

    if (tid < 140) {
        int j = tid / 20, k = tid % 20;
        float d0 = sm_cen[j+1][0] - sm_cen[j][0];
        float d1 = sm_cen[j+1][1] - sm_cen[j][1];
        sm_cen20[j][k] = d0 * up_w[k*2] + d1 * up_w[k*2 + 1] + up_b[k];
    }
    __syncthreads();
    if (tid < 140) {
        int i = tid / 20, k = tid % 20;
        float a = 0.f;
        #pragma unroll
        for (int j = 0; j < 7; j++) a += wW2[i*7 + j] * sm_cen20[j][k];
        sm_u2p[i][k] = ftanh(a) * wproj2[k];
    }
    __syncthreads();
    if (tid < 7) {
        float a = 0.f;
        #pragma unroll
        for (int k = 0; k < 20; k++) a += sm_u2p[tid][k];
        sm_s2[tid] = a;
    }
    __syncthreads();
    if (tid < 7) {
        float mx = sm_s2[0];
        #pragma unroll
        for (int i = 1; i < 7; i++) mx = fmaxf(mx, sm_s2[i]);
        float se = 0.f;
        #pragma unroll
        for (int i = 0; i < 7; i++) se += __expf(sm_s2[i] - mx);
        sm_att2[tid] = __expf(sm_s2[tid] - mx) / se;
    }
    __syncthreads();
    if (tid < 140) {
        int j = tid / 20, k = tid % 20;
        d_si[(bid*7 + j)*20 + k] = sm_cen20[j][k] * sm_att2[j];
    }
}

// ---------------- K4: conv1 (64->128, k=(1,3), s=(1,2), p=(0,1)) + BN1 partials
// Register-blocked: 1 thread = one (oc, i) row, 10 outputs.
__global__ void __launch_bounds__(128) k4_conv1(const float* __restrict__ w1) {
    __shared__ float s_si[C_*140];   // 8960 floats
    __shared__ float s_w[16*192];    // 3072 floats
    __shared__ float sp[112], sq[112];

    const int bid = blockIdx.x, tid = threadIdx.x;
    const int n = bid >> 3, gid = bid & 7;
    const int ocbase = gid * 16;

    const float* src = d_si + n * (C_*140);
    for (int i = tid; i < C_*140; i += 128) s_si[i] = src[i];
    for (int i = tid; i < 16*192; i += 128) s_w[i]  = w1[ocbase*192 + i];
    __syncthreads();

    if (tid < 112) {
        const int ocl = tid / 7, i = tid % 7;
        const int oc = ocbase + ocl;
        float acc[10];
        #pragma unroll
        for (int j = 0; j < 10; j++) acc[j] = 0.f;
        const float* wp = &s_w[ocl*192];

        #pragma unroll 4
        for (int ic = 0; ic < 64; ic++) {
            const float* xp = &s_si[ic*140 + i*20];
            float4 v0 = *(const float4*)(xp);
            float4 v1 = *(const float4*)(xp + 4);
            float4 v2 = *(const float4*)(xp + 8);
            float4 v3 = *(const float4*)(xp + 12);
            float4 v4 = *(const float4*)(xp + 16);
            float x[20] = {v0.x,v0.y,v0.z,v0.w, v1.x,v1.y,v1.z,v1.w,
                           v2.x,v2.y,v2.z,v2.w, v3.x,v3.y,v3.z,v3.w,
                           v4.x,v4.y,v4.z,v4.w};
            float w0 = wp[ic*3], wv1 = wp[ic*3+1], wv2 = wp[ic*3+2];
            acc[0] += x[0]*wv1 + x[1]*wv2;
            #pragma unroll
            for (int ow = 1; ow < 10; ow++)
                acc[ow] += x[2*ow-1]*w0 + x[2*ow]*wv1 + x[2*ow+1]*wv2;
        }
        float ssum = 0.f, ssq = 0.f;
        float* op = &d_x1[((n*ITER_ + oc)*7 + i)*10];
        #pragma unroll
        for (int ow = 0; ow < 10; ow++) {
            op[ow] = acc[ow]; ssum += acc[ow]; ssq += acc[ow]*acc[ow];
        }
        sp[tid] = ssum; sq[tid] = ssq;
    }
    __syncthreads();
    if (tid < 16) {
        double S = 0.0, Q = 0.0;
        #pragma unroll
        for (int j = 0; j < 7; j++) { S += sp[tid*7+j]; Q += sq[tid*7+j]; }
        d_p1s[n*ITER_ + ocbase + tid] = S;
        d_p1q[n*ITER_ + ocbase + tid] = Q;
    }
}

// ---------------- K5: BN1 finalize + tanh staging, once, padded stride-12 ------
// grid 256 = 16 n * 16 icg(8 ic). Stats reduction PARALLEL: 128 threads each
// load one (ch, n2) pair, width-16 shfl reduce (kills the serial 16-load chain).
__global__ void __launch_bounds__(128) k5_stage(const float* __restrict__ g1,
                                                const float* __restrict__ b1) {
    __shared__ float s_sc[8], s_sh[8];
    const int bid = blockIdx.x, tid = threadIdx.x;
    const int n = bid >> 4, icg = bid & 15;
    const int icbase = icg * 8;

    {
        // tid = ch_l*16 + n2 ; ch_l in [0,8), n2 in [0,16)
        const int ch_l = tid >> 4, n2 = tid & 15;
        const int ch = icbase + ch_l;
        double S = d_p1s[n2*ITER_ + ch];
        double Q = d_p1q[n2*ITER_ + ch];
        const unsigned fm = 0xffffffffu;
        #pragma unroll
        for (int off = 8; off > 0; off >>= 1) {
            S += __shfl_down_sync(fm, S, off, 16);
            Q += __shfl_down_sync(fm, Q, off, 16);
        }
        if (n2 == 0) {
            double cnt  = (double)(N_ * 7 * 10);
            double mean = S / cnt;
            double var  = Q / cnt - mean*mean;
            float sc = (float)((double)g1[ch] * rsqrt(var + EPSV));
            s_sc[ch_l] = sc;
            s_sh[ch_l] = b1[ch] - (float)mean * sc;
        }
    }
    __syncthreads();

    // 8 ic * 84 padded slots = 672 per block
    for (int idx = tid; idx < 8*84; idx += 128) {
        int icl = idx / 84, r = idx - icl*84;
        int i = r / 12, ow = r - i*12;
        const int ic = icbase + icl;
        float val = 0.f;
        if (ow < 10) {
            float xv = d_x1[((n*ITER_ + ic)*7 + i)*10 + ow];
            val = ftanh(xv * s_sc[icl] + s_sh[icl]);
        }
        d_x1t[(n*ITER_ + ic)*84 + i*12 + ow] = val;
    }
}

// ---------------- K67: conv2 + BN2 + tanh + width-mean, fused to final out ----
#define K67_SMEM (21504 + 1536 + 1120 + 2240 + 28 + 28 + 4 + 4)
__global__ void __launch_bounds__(256) k67_conv2(const float* __restrict__ w2,
                                                 const float* __restrict__ g2,
                                                 const float* __restrict__ b2,
                                                 float* __restrict__ out) {
    extern __shared__ float sm7[];
    float* s_buf  = sm7;                  // 2 * 10752
    float* s_w    = sm7 + 21504;          // 1536
    float* s_part = sm7 + 23040;          // 8*28*5 = 1120
    float* s_x2   = sm7 + 24160;          // 4*16*35 = 2240
    float* s_ss   = sm7 + 26400;          // 28
    float* s_sq   = sm7 + 26428;          // 28
    float* s_sc   = sm7 + 26456;          // 4
    float* s_sh   = sm7 + 26460;          // 4

    const int tid = threadIdx.x;
    const int ocbase = blockIdx.x * 4;

    for (int i = tid; i < 4*384; i += 256) s_w[i] = w2[ocbase*384 + i];

    {
        const float* src = d_x1t;
        for (int i = tid; i < 2688; i += 256) {
            unsigned dst = (unsigned)__cvta_generic_to_shared(s_buf + i*4);
            asm volatile("cp.async.cg.shared.global [%0], [%1], 16;"
                         :: "r"(dst), "l"(src + i*4));
        }
        asm volatile("cp.async.commit_group;" ::: "memory");
    }

    const int g   = tid / 28;
    const int rr  = tid - g*28;
    const int ocl = rr / 7;
    const int ii  = rr - ocl*7;
    float accS = 0.f, accQ = 0.f;

    for (int n = 0; n < 16; n++) {
        asm volatile("cp.async.wait_group 0;" ::: "memory");
        __syncthreads();
        const float* s_x = s_buf + (n & 1) * 10752;

        if (n < 15) {
            float* nb = s_buf + ((n + 1) & 1) * 10752;
            const float* src = d_x1t + (n + 1) * 10752;
            for (int i = tid; i < 2688; i += 256) {
                unsigned dst = (unsigned)__cvta_generic_to_shared(nb + i*4);
                asm volatile("cp.async.cg.shared.global [%0], [%1], 16;"
                             :: "r"(dst), "l"(src + i*4));
            }
            asm volatile("cp.async.commit_group;" ::: "memory");
        }

        if (tid < 224) {
            float acc[5];
            #pragma unroll
            for (int j = 0; j < 5; j++) acc[j] = 0.f;
            const float* wp = &s_w[ocl*384];
            const int ic0 = g * 16;
            #pragma unroll 4
            for (int ic = ic0; ic < ic0 + 16; ic++) {
                const float* xp = &s_x[ic*84 + ii*12];
                float4 v0 = *(const float4*)(xp);
                float4 v1 = *(const float4*)(xp + 4);
                float2 v2 = *(const float2*)(xp + 8);
                float x[10] = {v0.x,v0.y,v0.z,v0.w, v1.x,v1.y,v1.z,v1.w, v2.x,v2.y};
                float w0 = wp[ic*3], wv1 = wp[ic*3+1], wv2 = wp[ic*3+2];
                acc[0] += x[0]*wv1 + x[1]*wv2;
                #pragma unroll
                for (int ow = 1; ow < 5; ow++)
                    acc[ow] += x[2*ow-1]*w0 + x[2*ow]*wv1 + x[2*ow+1]*wv2;
            }
            float* pp = &s_part[(g*28 + ocl*7 + ii)*5];
            #pragma unroll
            for (int ow = 0; ow < 5; ow++) pp[ow] = acc[ow];
        }
        __syncthreads();
        if (tid < 28) {
            const int oc2 = tid / 7, i2 = tid - oc2*7;
            #pragma unroll
            for (int ow = 0; ow < 5; ow++) {
                float a = 0.f;
                #pragma unroll
                for (int gg = 0; gg < 8; gg++)
                    a += s_part[(gg*28 + oc2*7 + i2)*5 + ow];
                s_x2[(oc2*16 + n)*35 + i2*5 + ow] = a;
                accS += a; accQ += a*a;
            }
        }
    }
    __syncthreads();
    if (tid < 28) { s_ss[tid] = accS; s_sq[tid] = accQ; }
    __syncthreads();
    if (tid < 4) {
        float S = 0.f, Q = 0.f;
        #pragma unroll
        for (int j = 0; j < 7; j++) { S += s_ss[tid*7+j]; Q += s_sq[tid*7+j]; }
        double cnt  = (double)(N_ * 7 * 5);
        double mean = (double)S / cnt;
        double var  = (double)Q / cnt - mean*mean;
        float sc = (float)((double)g2[ocbase + tid] * rsqrt(var + EPSV));
        s_sc[tid] = sc;
        s_sh[tid] = b2[ocbase + tid] - (float)mean * sc;
    }
    __syncthreads();
    for (int t = tid; t < 448; t += 256) {
        int n = t / 28, r2 = t - n*28, oc2 = r2 / 7, i2 = r2 - oc2*7;
        const float* xp = &s_x2[(oc2*16 + n)*35 + i2*5];
        float sc = s_sc[oc2], sh = s_sh[oc2];
        float a = 0.f;
        #pragma unroll
        for (int w = 0; w < 5; w++) a += ftanh(xp[w] * sc + sh);
        out[(n*OUT_ + (ocbase + oc2))*7 + i2] = a * 0.2f;
    }
}

// ---------------- launcher ----------------------------------------------------
extern "C" void kernel_launch(void* const* d_in, const int* in_sizes, int n_in,
                              void* d_out, int out_size) {
    (void)in_sizes; (void)n_in; (void)out_size;
    const float* h      = (const float*)d_in[0];
    const float* g0     = (const float*)d_in[1];
    const float* b0     = (const float*)d_in[2];
    const float* up_w   = (const float*)d_in[3];
    const float* up_b   = (const float*)d_in[4];
    const float* up2_w  = (const float*)d_in[5];
    const float* up2_b  = (const float*)d_in[6];
    const float* up3_w  = (const float*)d_in[7];
    const float* up3_b  = (const float*)d_in[8];
    const float* wW     = (const float*)d_in[9];
    const float* wproj  = (const float*)d_in[10];
    const float* wW2    = (const float*)d_in[11];
    const float* wproj2 = (const float*)d_in[12];
    const float* w1     = (const float*)d_in[13];
    const float* g1     = (const float*)d_in[14];
    const float* b1     = (const float*)d_in[15];
    const float* w2     = (const float*)d_in[16];
    const float* g2     = (const float*)d_in[17];
    const float* b2     = (const float*)d_in[18];
    float* out = (float*)d_out;

    cudaFuncSetAttribute(k67_conv2, cudaFuncAttributeMaxDynamicSharedMemorySize,
                         K67_SMEM * 4);

    k1_top5<<<1024, 256>>>(h, g0);
    k3_attn<<<N_*C_, 256>>>(g0, b0, up_w, up_b, up2_w, up2_b, up3_w, up3_b,
                            wW, wproj, wW2, wproj2);
    k4_conv1<<<128, 128>>>(w1);
    k5_stage<<<256, 128>>>(g1, b1);
    k67_conv2<<<64, 256, K67_SMEM * 4>>>(w2, g2, b2, out);
}

// round 11
// speedup vs baseline: 1.3363x; 1.1584x over previous
#include <cuda_runtime.h>
#include <math.h>
#include <stdint.h>
#include <float.h>

#define N_    16
#define C_    64
#define F_    8
#define HW_   3136
#define NROWS (N_*C_*F_)     // 8192
#define ITER_ 128
#define OUT_  256
#define EPSV  1e-5

typedef unsigned long long ull;

// ---------------- scratch (static device memory; rewritten fully each run) ----
__device__ float  d_top5[NROWS*5];
__device__ double d_rsum[NROWS];
__device__ double d_rsq [NROWS];
__device__ float  d_si  [N_*C_*7*20];     // attention output, conv1 input
__device__ float  d_x1  [N_*ITER_*7*10];  // conv1 output (pre-BN)
__device__ float  d_x1t [N_*ITER_*7*12];  // tanh(BN1(x1)), padded rows of 12
__device__ double d_p1s [N_*ITER_];
__device__ double d_p1q [N_*ITER_];

// ---------------- helpers -----------------------------------------------------
__device__ __forceinline__ float ftanh(float x) {
    float y;
    asm("tanh.approx.f32 %0, %1;" : "=f"(y) : "f"(x));
    return y;
}
__device__ __forceinline__ ull pk2(float a, float b) {
    ull r; asm("mov.b64 %0, {%1, %2};" : "=l"(r) : "f"(a), "f"(b)); return r;
}
__device__ __forceinline__ void upk2(ull v, float& a, float& b) {
    asm("mov.b64 {%0, %1}, %2;" : "=f"(a), "=f"(b) : "l"(v));
}
__device__ __forceinline__ ull add2_(ull a, ull b) {
    ull r; asm("add.rn.f32x2 %0, %1, %2;" : "=l"(r) : "l"(a), "l"(b)); return r;
}
__device__ __forceinline__ ull fma2_(ull a, ull b, ull c) {
    ull r; asm("fma.rn.f32x2 %0, %1, %2, %3;" : "=l"(r) : "l"(a), "l"(b), "l"(c)); return r;
}

__device__ __forceinline__ void ins5(float* kk, float key) {
    if (key > kk[4]) {
        kk[4] = key;
        if (kk[4] > kk[3]) { float t=kk[4]; kk[4]=kk[3]; kk[3]=t;
        if (kk[3] > kk[2]) { t=kk[3]; kk[3]=kk[2]; kk[2]=t;
        if (kk[2] > kk[1]) { t=kk[2]; kk[2]=kk[1]; kk[1]=t;
        if (kk[1] > kk[0]) { t=kk[1]; kk[1]=kk[0]; kk[0]=t; } } } }
    }
}

// merge two sorted-descending 5-lists, keep top 5 (in a)
__device__ __forceinline__ void merge5(float* a, const float* b) {
    float r[5]; int ia = 0, ib = 0;
    #pragma unroll
    for (int t = 0; t < 5; t++) {
        float av = a[ia], bv = b[ib];
        if (av >= bv) { r[t] = av; ia++; } else { r[t] = bv; ib++; }
    }
    #pragma unroll
    for (int t = 0; t < 5; t++) a[t] = r[t];
}

// process 8 elements (two float4s): packed sums + amortized top-5 check
template<bool NEG>
__device__ __forceinline__ void proc8(const float4 a, const float4 b,
                                      ull& s0, ull& s1, ull& q0, ull& q1,
                                      float* kk) {
    ull p0 = pk2(a.x, a.y), p1 = pk2(a.z, a.w);
    ull p2 = pk2(b.x, b.y), p3 = pk2(b.z, b.w);
    s0 = add2_(s0, p0); s1 = add2_(s1, p1);
    s0 = add2_(s0, p2); s1 = add2_(s1, p3);
    q0 = fma2_(p0, p0, q0); q1 = fma2_(p1, p1, q1);
    q0 = fma2_(p2, p2, q0); q1 = fma2_(p3, p3, q1);
    float k0, k1v, k2, k3, k4, k5, k6, k7;
    if (NEG) { k0=-a.x; k1v=-a.y; k2=-a.z; k3=-a.w; k4=-b.x; k5=-b.y; k6=-b.z; k7=-b.w; }
    else     { k0= a.x; k1v= a.y; k2= a.z; k3= a.w; k4= b.x; k5= b.y; k6= b.z; k7= b.w; }
    float m = fmaxf(fmaxf(fmaxf(k0,k1v), fmaxf(k2,k3)),
                    fmaxf(fmaxf(k4,k5),  fmaxf(k6,k7)));
    if (m > kk[4]) {
        ins5(kk,k0); ins5(kk,k1v); ins5(kk,k2); ins5(kk,k3);
        ins5(kk,k4); ins5(kk,k5);  ins5(kk,k6); ins5(kk,k7);
    }
}

template<bool NEG>
__device__ __forceinline__ void proc4(const float4 a,
                                      ull& s0, ull& q0, float* kk) {
    ull p0 = pk2(a.x, a.y), p1 = pk2(a.z, a.w);
    s0 = add2_(s0, p0); s0 = add2_(s0, p1);
    q0 = fma2_(p0, p0, q0); q0 = fma2_(p1, p1, q0);
    float k0, k1v, k2, k3;
    if (NEG) { k0=-a.x; k1v=-a.y; k2=-a.z; k3=-a.w; }
    else     { k0= a.x; k1v= a.y; k2= a.z; k3= a.w; }
    float m = fmaxf(fmaxf(k0,k1v), fmaxf(k2,k3));
    if (m > kk[4]) { ins5(kk,k0); ins5(kk,k1v); ins5(kk,k2); ins5(kk,k3); }
}

// ---------------- K1: warp-per-row: top5 + sum/sumsq, packed f32x2 math --------
__global__ void __launch_bounds__(256) k1_top5(const float* __restrict__ h,
                                               const float* __restrict__ g0) {
    const int wid  = threadIdx.x >> 5, lane = threadIdx.x & 31;
    const int row  = blockIdx.x * 8 + wid;
    const int c    = (row >> 3) & (C_ - 1);
    const bool neg = (g0[c] < 0.f);

    const float4* p = (const float4*)(h + (size_t)row * HW_);

    ull s0 = 0ull, s1 = 0ull, q0 = 0ull, q1 = 0ull;   // packed (0.f, 0.f)
    float kk[5];
    #pragma unroll
    for (int j = 0; j < 5; j++) kk[j] = -FLT_MAX;

    if (!neg) {
        #pragma unroll 4
        for (int t = 0; t < 12; t++) {
            float4 a = p[lane + 64*t];
            float4 b = p[lane + 64*t + 32];
            proc8<false>(a, b, s0, s1, q0, q1, kk);
        }
        if (lane < 16) proc4<false>(p[768 + lane], s0, q0, kk);
    } else {
        #pragma unroll 4
        for (int t = 0; t < 12; t++) {
            float4 a = p[lane + 64*t];
            float4 b = p[lane + 64*t + 32];
            proc8<true>(a, b, s0, s1, q0, q1, kk);
        }
        if (lane < 16) proc4<true>(p[768 + lane], s0, q0, kk);
    }

    // combine packed halves
    ull st = add2_(s0, s1);
    ull qt = add2_(q0, q1);
    float slo, shi, qlo, qhi;
    upk2(st, slo, shi); upk2(qt, qlo, qhi);
    float s = slo + shi, q = qlo + qhi;

    // warp butterfly reduce
    const unsigned m = 0xffffffffu;
    #pragma unroll
    for (int off = 16; off > 0; off >>= 1) {
        float ob[5];
        #pragma unroll
        for (int j = 0; j < 5; j++) ob[j] = __shfl_xor_sync(m, kk[j], off);
        merge5(kk, ob);
        s += __shfl_xor_sync(m, s, off);
        q += __shfl_xor_sync(m, q, off);
    }

    if (lane == 0) {
        const float sel = neg ? -1.f : 1.f;
        #pragma unroll
        for (int j = 0; j < 5; j++) d_top5[row*5 + j] = kk[j] * sel;
        d_rsum[row] = (double)s;
        d_rsq [row] = (double)q;
    }
}

// ---------------- K3: per-(n,c) block: BN0 finalize + attention pipeline -------
__global__ void __launch_bounds__(256) k3_attn(
    const float* __restrict__ g0,  const float* __restrict__ b0,
    const float* __restrict__ up_w, const float* __restrict__ up_b,
    const float* __restrict__ up2_w, const float* __restrict__ up2_b,
    const float* __restrict__ up3_w, const float* __restrict__ up3_b,
    const float* __restrict__ wW,   const float* __restrict__ wproj,
    const float* __restrict__ wW2,  const float* __restrict__ wproj2) {

    const int bid = blockIdx.x;     // n*64 + c
    const int tid = threadIdx.x;
    const int n = bid >> 6, c = bid & 63;

    __shared__ double s1[128], s2[128];
    __shared__ float  s_scale, s_shift;
    __shared__ float  sm_t[8][25], sm_u[8][25];
    __shared__ float  sm_s5[8][5], sm_w5[8][5];
    __shared__ float  sm_cen[8][2];
    __shared__ float  sm_cen20[7][20], sm_u2p[7][20];
    __shared__ float  sm_s2[7], sm_att2[7];

    if (tid < 128) {
        int n2 = tid >> 3, f = tid & 7;
        int r = (n2*C_ + c)*F_ + f;
        s1[tid] = d_rsum[r];
        s2[tid] = d_rsq [r];
    }
    __syncthreads();
    for (int st = 64; st > 0; st >>= 1) {
        if (tid < st) { s1[tid] += s1[tid+st]; s2[tid] += s2[tid+st]; }
        __syncthreads();
    }
    if (tid == 0) {
        double cnt  = (double)(N_ * F_ * HW_);
        double mean = s1[0] / cnt;
        double var  = s2[0] / cnt - mean*mean;
        double inv  = rsqrt(var + EPSV);
        float  sc   = (float)((double)g0[c] * inv);
        s_scale = sc;
        s_shift = b0[c] - (float)mean * sc;
    }
    __syncthreads();

    const int f = tid >> 5, lane = tid & 31;   // 8 warps = 8 frames
    const int row = (n*C_ + c)*F_ + f;

    float v[5];
    #pragma unroll
    for (int j = 0; j < 5; j++) v[j] = d_top5[row*5 + j] * s_scale + s_shift;

    if (lane < 25) {
        float a = up2_b[lane];
        #pragma unroll
        for (int j = 0; j < 5; j++) a += v[j] * up2_w[lane*5 + j];
        sm_t[f][lane] = a;
    }
    __syncwarp();
    if (lane < 25) {
        float a = 0.f;
        #pragma unroll
        for (int k = 0; k < 25; k++) a += sm_t[f][k] * wW[k*25 + lane];
        sm_u[f][lane] = ftanh(a);
    }
    __syncwarp();
    if (lane < 5) {
        float a = 0.f;
        #pragma unroll
        for (int k = 0; k < 25; k++) a += sm_u[f][k] * wproj[k*5 + lane];
        sm_s5[f][lane] = a;
    }
    __syncwarp();
    if (lane < 5) {
        float mx = sm_s5[f][0];
        #pragma unroll
        for (int j = 1; j < 5; j++) mx = fmaxf(mx, sm_s5[f][j]);
        float se = 0.f;
        #pragma unroll
        for (int j = 0; j < 5; j++) se += __expf(sm_s5[f][j] - mx);
        float att = __expf(sm_s5[f][lane] - mx) / se;
        float a = up3_b[lane];
        #pragma unroll
        for (int k = 0; k < 25; k++) a += sm_t[f][k] * up3_w[lane*25 + k];
        sm_w5[f][lane] = a * att;
    }
    __syncwarp();
    float p0 = 0.f, p1 = 0.f;
    if (lane < 25) {
        float a = up2_b[lane];
        #pragma unroll
        for (int j = 0; j < 5; j++) a += sm_w5[f][j] * up2_w[lane*5 + j];
        p0 = a * (float)(lane / 5);
        p1 = a * (float)(lane % 5);
    }
    #pragma unroll
    for (int off = 16; off > 0; off >>= 1) {
        p0 += __shfl_down_sync(0xffffffffu, p0, off);
        p1 += __shfl_down_sync(0xffffffffu, p1, off);
    }
    if (lane == 0) { sm_cen[f][0] = p0; sm_cen[f][1] = p1; }
    __syncthreads();

    if (tid < 140) {
        int j = tid / 20, k = tid % 20;
        float d0 = sm_cen[j+1][0] - sm_cen[j][0];
        float d1 = sm_cen[j+1][1] - sm_cen[j][1];
        sm_cen20[j][k] = d0 * up_w[k*2] + d1 * up_w[k*2 + 1] + up_b[k];
    }
    __syncthreads();
    if (tid < 140) {
        int i = tid / 20, k = tid % 20;
        float a = 0.f;
        #pragma unroll
        for (int j = 0; j < 7; j++) a += wW2[i*7 + j] * sm_cen20[j][k];
        sm_u2p[i][k] = ftanh(a) * wproj2[k];
    }
    __syncthreads();
    if (tid < 7) {
        float a = 0.f;
        #pragma unroll
        for (int k = 0; k < 20; k++) a += sm_u2p[tid][k];
        sm_s2[tid] = a;
    }
    __syncthreads();
    if (tid < 7) {
        float mx = sm_s2[0];
        #pragma unroll
        for (int i = 1; i < 7; i++) mx = fmaxf(mx, sm_s2[i]);
        float se = 0.f;
        #pragma unroll
        for (int i = 0; i < 7; i++) se += __expf(sm_s2[i] - mx);
        sm_att2[tid] = __expf(sm_s2[tid] - mx) / se;
    }
    __syncthreads();
    if (tid < 140) {
        int j = tid / 20, k = tid % 20;
        d_si[(bid*7 + j)*20 + k] = sm_cen20[j][k] * sm_att2[j];
    }
}

// ---------------- K4: conv1 (64->128, k=(1,3), s=(1,2), p=(0,1)) + BN1 partials
// Register-blocked: 1 thread = one (oc, i) row, 10 outputs.
__global__ void __launch_bounds__(128) k4_conv1(const float* __restrict__ w1) {
    __shared__ float s_si[C_*140];   // 8960 floats
    __shared__ float s_w[16*192];    // 3072 floats
    __shared__ float sp[112], sq[112];

    const int bid = blockIdx.x, tid = threadIdx.x;
    const int n = bid >> 3, gid = bid & 7;
    const int ocbase = gid * 16;

    const float* src = d_si + n * (C_*140);
    for (int i = tid; i < C_*140; i += 128) s_si[i] = src[i];
    for (int i = tid; i < 16*192; i += 128) s_w[i]  = w1[ocbase*192 + i];
    __syncthreads();

    if (tid < 112) {
        const int ocl = tid / 7, i = tid % 7;
        const int oc = ocbase + ocl;
        float acc[10];
        #pragma unroll
        for (int j = 0; j < 10; j++) acc[j] = 0.f;
        const float* wp = &s_w[ocl*192];

        #pragma unroll 4
        for (int ic = 0; ic < 64; ic++) {
            const float* xp = &s_si[ic*140 + i*20];
            float4 v0 = *(const float4*)(xp);
            float4 v1 = *(const float4*)(xp + 4);
            float4 v2 = *(const float4*)(xp + 8);
            float4 v3 = *(const float4*)(xp + 12);
            float4 v4 = *(const float4*)(xp + 16);
            float x[20] = {v0.x,v0.y,v0.z,v0.w, v1.x,v1.y,v1.z,v1.w,
                           v2.x,v2.y,v2.z,v2.w, v3.x,v3.y,v3.z,v3.w,
                           v4.x,v4.y,v4.z,v4.w};
            float w0 = wp[ic*3], wv1 = wp[ic*3+1], wv2 = wp[ic*3+2];
            acc[0] += x[0]*wv1 + x[1]*wv2;
            #pragma unroll
            for (int ow = 1; ow < 10; ow++)
                acc[ow] += x[2*ow-1]*w0 + x[2*ow]*wv1 + x[2*ow+1]*wv2;
        }
        float ssum = 0.f, ssq = 0.f;
        float* op = &d_x1[((n*ITER_ + oc)*7 + i)*10];
        #pragma unroll
        for (int ow = 0; ow < 10; ow++) {
            op[ow] = acc[ow]; ssum += acc[ow]; ssq += acc[ow]*acc[ow];
        }
        sp[tid] = ssum; sq[tid] = ssq;
    }
    __syncthreads();
    if (tid < 16) {
        double S = 0.0, Q = 0.0;
        #pragma unroll
        for (int j = 0; j < 7; j++) { S += sp[tid*7+j]; Q += sq[tid*7+j]; }
        d_p1s[n*ITER_ + ocbase + tid] = S;
        d_p1q[n*ITER_ + ocbase + tid] = Q;
    }
}

// ---------------- K5: BN1 finalize + tanh staging, once, padded stride-12 ------
// grid 256 = 16 n * 16 icg(8 ic). Stats reduction parallel (128 thr, shfl w16);
// staging stores vectorized as 3x float4 per padded 12-row.
__global__ void __launch_bounds__(128) k5_stage(const float* __restrict__ g1,
                                                const float* __restrict__ b1) {
    __shared__ float s_sc[8], s_sh[8];
    const int bid = blockIdx.x, tid = threadIdx.x;
    const int n = bid >> 4, icg = bid & 15;
    const int icbase = icg * 8;

    {
        // tid = ch_l*16 + n2 ; ch_l in [0,8), n2 in [0,16)
        const int ch_l = tid >> 4, n2 = tid & 15;
        const int ch = icbase + ch_l;
        double S = d_p1s[n2*ITER_ + ch];
        double Q = d_p1q[n2*ITER_ + ch];
        const unsigned fm = 0xffffffffu;
        #pragma unroll
        for (int off = 8; off > 0; off >>= 1) {
            S += __shfl_down_sync(fm, S, off, 16);
            Q += __shfl_down_sync(fm, Q, off, 16);
        }
        if (n2 == 0) {
            double cnt  = (double)(N_ * 7 * 10);
            double mean = S / cnt;
            double var  = Q / cnt - mean*mean;
            float sc = (float)((double)g1[ch] * rsqrt(var + EPSV));
            s_sc[ch_l] = sc;
            s_sh[ch_l] = b1[ch] - (float)mean * sc;
        }
    }
    __syncthreads();

    // 8 ic * 7 i = 56 padded rows of 12 -> 3 float4 stores each
    for (int r0 = tid; r0 < 56; r0 += 128) {
        int icl = r0 / 7, i = r0 - icl*7;
        const int ic = icbase + icl;
        const float* rp = &d_x1[((n*ITER_ + ic)*7 + i)*10];
        float sc = s_sc[icl], sh = s_sh[icl];
        float y[12];
        #pragma unroll
        for (int ow = 0; ow < 10; ow++) y[ow] = ftanh(rp[ow]*sc + sh);
        y[10] = 0.f; y[11] = 0.f;
        float4* wp4 = (float4*)&d_x1t[(n*ITER_ + ic)*84 + i*12];
        wp4[0] = make_float4(y[0], y[1], y[2],  y[3]);
        wp4[1] = make_float4(y[4], y[5], y[6],  y[7]);
        wp4[2] = make_float4(y[8], y[9], y[10], y[11]);
    }
}

// ---------------- K67: conv2 + BN2 + tanh + width-mean, fused to final out ----
#define K67_SMEM (21504 + 1536 + 1120 + 2240 + 28 + 28 + 4 + 4)
__global__ void __launch_bounds__(256) k67_conv2(const float* __restrict__ w2,
                                                 const float* __restrict__ g2,
                                                 const float* __restrict__ b2,
                                                 float* __restrict__ out) {
    extern __shared__ float sm7[];
    float* s_buf  = sm7;                  // 2 * 10752
    float* s_w    = sm7 + 21504;          // 1536
    float* s_part = sm7 + 23040;          // 8*28*5 = 1120
    float* s_x2   = sm7 + 24160;          // 4*16*35 = 2240
    float* s_ss   = sm7 + 26400;          // 28
    float* s_sq   = sm7 + 26428;          // 28
    float* s_sc   = sm7 + 26456;          // 4
    float* s_sh   = sm7 + 26460;          // 4

    const int tid = threadIdx.x;
    const int ocbase = blockIdx.x * 4;

    for (int i = tid; i < 4*384; i += 256) s_w[i] = w2[ocbase*384 + i];

    {
        const float* src = d_x1t;
        for (int i = tid; i < 2688; i += 256) {
            unsigned dst = (unsigned)__cvta_generic_to_shared(s_buf + i*4);
            asm volatile("cp.async.cg.shared.global [%0], [%1], 16;"
                         :: "r"(dst), "l"(src + i*4));
        }
        asm volatile("cp.async.commit_group;" ::: "memory");
    }

    const int g   = tid / 28;
    const int rr  = tid - g*28;
    const int ocl = rr / 7;
    const int ii  = rr - ocl*7;
    float accS = 0.f, accQ = 0.f;

    for (int n = 0; n < 16; n++) {
        asm volatile("cp.async.wait_group 0;" ::: "memory");
        __syncthreads();
        const float* s_x = s_buf + (n & 1) * 10752;

        if (n < 15) {
            float* nb = s_buf + ((n + 1) & 1) * 10752;
            const float* src = d_x1t + (n + 1) * 10752;
            for (int i = tid; i < 2688; i += 256) {
                unsigned dst = (unsigned)__cvta_generic_to_shared(nb + i*4);
                asm volatile("cp.async.cg.shared.global [%0], [%1], 16;"
                             :: "r"(dst), "l"(src + i*4));
            }
            asm volatile("cp.async.commit_group;" ::: "memory");
        }

        if (tid < 224) {
            float acc[5];
            #pragma unroll
            for (int j = 0; j < 5; j++) acc[j] = 0.f;
            const float* wp = &s_w[ocl*384];
            const int ic0 = g * 16;
            #pragma unroll 4
            for (int ic = ic0; ic < ic0 + 16; ic++) {
                const float* xp = &s_x[ic*84 + ii*12];
                float4 v0 = *(const float4*)(xp);
                float4 v1 = *(const float4*)(xp + 4);
                float2 v2 = *(const float2*)(xp + 8);
                float x[10] = {v0.x,v0.y,v0.z,v0.w, v1.x,v1.y,v1.z,v1.w, v2.x,v2.y};
                float w0 = wp[ic*3], wv1 = wp[ic*3+1], wv2 = wp[ic*3+2];
                acc[0] += x[0]*wv1 + x[1]*wv2;
                #pragma unroll
                for (int ow = 1; ow < 5; ow++)
                    acc[ow] += x[2*ow-1]*w0 + x[2*ow]*wv1 + x[2*ow+1]*wv2;
            }
            float* pp = &s_part[(g*28 + ocl*7 + ii)*5];
            #pragma unroll
            for (int ow = 0; ow < 5; ow++) pp[ow] = acc[ow];
        }
        __syncthreads();
        if (tid < 28) {
            const int oc2 = tid / 7, i2 = tid - oc2*7;
            #pragma unroll
            for (int ow = 0; ow < 5; ow++) {
                float a = 0.f;
                #pragma unroll
                for (int gg = 0; gg < 8; gg++)
                    a += s_part[(gg*28 + oc2*7 + i2)*5 + ow];
                s_x2[(oc2*16 + n)*35 + i2*5 + ow] = a;
                accS += a; accQ += a*a;
            }
        }
    }
    __syncthreads();
    if (tid < 28) { s_ss[tid] = accS; s_sq[tid] = accQ; }
    __syncthreads();
    if (tid < 4) {
        float S = 0.f, Q = 0.f;
        #pragma unroll
        for (int j = 0; j < 7; j++) { S += s_ss[tid*7+j]; Q += s_sq[tid*7+j]; }
        double cnt  = (double)(N_ * 7 * 5);
        double mean = (double)S / cnt;
        double var  = (double)Q / cnt - mean*mean;
        float sc = (float)((double)g2[ocbase + tid] * rsqrt(var + EPSV));
        s_sc[tid] = sc;
        s_sh[tid] = b2[ocbase + tid] - (float)mean * sc;
    }
    __syncthreads();
    for (int t = tid; t < 448; t += 256) {
        int n = t / 28, r2 = t - n*28, oc2 = r2 / 7, i2 = r2 - oc2*7;
        const float* xp = &s_x2[(oc2*16 + n)*35 + i2*5];
        float sc = s_sc[oc2], sh = s_sh[oc2];
        float a = 0.f;
        #pragma unroll
        for (int w = 0; w < 5; w++) a += ftanh(xp[w] * sc + sh);
        out[(n*OUT_ + (ocbase + oc2))*7 + i2] = a * 0.2f;
    }
}

// ---------------- launcher ----------------------------------------------------
extern "C" void kernel_launch(void* const* d_in, const int* in_sizes, int n_in,
                              void* d_out, int out_size) {
    (void)in_sizes; (void)n_in; (void)out_size;
    const float* h      = (const float*)d_in[0];
    const float* g0     = (const float*)d_in[1];
    const float* b0     = (const float*)d_in[2];
    const float* up_w   = (const float*)d_in[3];
    const float* up_b   = (const float*)d_in[4];
    const float* up2_w  = (const float*)d_in[5];
    const float* up2_b  = (const float*)d_in[6];
    const float* up3_w  = (const float*)d_in[7];
    const float* up3_b  = (const float*)d_in[8];
    const float* wW     = (const float*)d_in[9];
    const float* wproj  = (const float*)d_in[10];
    const float* wW2    = (const float*)d_in[11];
    const float* wproj2 = (const float*)d_in[12];
    const float* w1     = (const float*)d_in[13];
    const float* g1     = (const float*)d_in[14];
    const float* b1     = (const float*)d_in[15];
    const float* w2     = (const float*)d_in[16];
    const float* g2     = (const float*)d_in[17];
    const float* b2     = (const float*)d_in[18];
    float* out = (float*)d_out;

    cudaFuncSetAttribute(k67_conv2, cudaFuncAttributeMaxDynamicSharedMemorySize,
                         K67_SMEM * 4);

    k1_top5<<<1024, 256>>>(h, g0);
    k3_attn<<<N_*C_, 256>>>(g0, b0, up_w, up_b, up2_w, up2_b, up3_w, up3_b,
                            wW, wproj, wW2, wproj2);
    k4_conv1<<<128, 128>>>(w1);
    k5_stage<<<256, 128>>>(g1, b1);
    k67_conv2<<<64, 256, K67_SMEM * 4>>>(w2, g2, b2, out);
}